// round 13
// baseline (speedup 1.0000x reference)
#include <cuda_runtime.h>

// CRF Viterbi decode: B=256, T=512, N=128. Output dtype = FLOAT32.
// R13 vs R12: length-aware scheduling. Classify kernel ranks sequences by
// length; CTA c runs pair (sorted[c], sorted[255-c]) as two independent
// 128-thread halves with named barriers -> per-SM work ~L_max+L_min ~ 513
// steps instead of worst-case ~1024. Forward/backward cores unchanged.

constexpr int NTAG = 128;
constexpr int TMAX = 512;
constexpr int BMAX = 256;
constexpr int TRS  = 132;   // padded smem row stride (floats) for trT

__device__ float g_hist[(long long)BMAX * TMAX * NTAG];  // 64 MB state history
__device__ int g_perm[3];     // [0]=logits idx, [1]=transitions idx, [2]=seqlen idx
__device__ int g_sorted[BMAX]; // g_sorted[rank] = seq index (desc by length)

#define ADD_F32X2(out, a, b) \
    asm("add.rn.f32x2 %0, %1, %2;" : "=l"(out) : "l"(a), "l"(b))
#define PACK_F32X2(out, lo, hi) \
    asm("mov.b64 %0, {%1, %2};" : "=l"(out) : "r"(lo), "r"(hi))
#define UNPACK_F32X2(lo, hi, in) \
    asm("mov.b64 {%0, %1}, %2;" : "=r"(lo), "=r"(hi) : "l"(in))

__device__ __forceinline__ void half_bar(int id) {
    asm volatile("bar.sync %0, %1;" :: "r"(id), "r"(128) : "memory");
}

__global__ void classify_kernel(const void* p0, const void* p1, const void* p2)
{
    const int tid = threadIdx.x;
    __shared__ int sL[BMAX];
    const void* ptrs[3] = {p0, p1, p2};

    if (tid == 0) {
        int seq_idx = -1;
        float meanabs[3];
        for (int k = 0; k < 3; ++k) {
            const int*   wi = (const int*)ptrs[k];
            const float* wf = (const float*)ptrs[k];
            bool all_len = true;
            float s = 0.0f;
            for (int i = 0; i < 64; ++i) {
                int v = wi[i];
                if (v < 1 || v > TMAX) all_len = false;
                s += fabsf(wf[i]);
            }
            meanabs[k] = s * (1.0f / 64.0f);
            if (all_len && seq_idx < 0) seq_idx = k;
        }
        if (seq_idx < 0) seq_idx = 2;

        int a = -1, c = -1;
        for (int k = 0; k < 3; ++k)
            if (k != seq_idx) { if (a < 0) a = k; else c = k; }
        int tr = (meanabs[a] < meanabs[c]) ? a : c;
        int lg = (tr == a) ? c : a;
        g_perm[0] = lg; g_perm[1] = tr; g_perm[2] = seq_idx;
    }
    __syncthreads();

    // Rank sequences by length (descending, ties by index) -> g_sorted.
    const int* seqlen = (const int*)ptrs[g_perm[2]];
    int Li = seqlen[tid];
    if (Li < 1) Li = 1;
    if (Li > TMAX) Li = TMAX;
    sL[tid] = Li;
    __syncthreads();

    int r = 0;
    for (int k = 0; k < BMAX; ++k) {
        int Lk = sL[k];
        r += (Lk > Li) || (Lk == Li && k < tid);
    }
    g_sorted[r] = tid;
}

// Monotone order-preserving float->uint (equal floats -> equal uints).
__device__ __forceinline__ unsigned ordered_u32(float f) {
    unsigned u = __float_as_uint(f);
    return ((int)u >= 0) ? (u | 0x80000000u) : ~u;
}

__global__ void __launch_bounds__(256)
crf_fused_kernel(const void* p0, const void* p1, const void* p2,
                 float* __restrict__ out)
{
    const void* ptrs[3] = {p0, p1, p2};
    const float* logits = (const float*)ptrs[g_perm[0]];
    const float* trans  = (const float*)ptrs[g_perm[1]];
    const int*   seqlen = (const int*)ptrs[g_perm[2]];

    extern __shared__ __align__(16) float dsm[];
    // layout: [stA 2*128][stB 2*128][sm_tr 128*TRS]
    float* sm_tr = dsm + 4 * NTAG;

    const int tid  = threadIdx.x;
    const int half = tid >> 7;            // 0 = A, 1 = B
    const int j    = tid & 127;           // tag within half
    const int bar  = 1 + half;            // named barrier per half
    float* st = dsm + half * 2 * NTAG;

    const int c = blockIdx.x;
    const int b = half ? g_sorted[BMAX - 1 - c] : g_sorted[c];

    // Transition column j packed into 64 x f32x2; half A also builds sm_tr.
    unsigned long long trp[64];
#pragma unroll
    for (int m = 0; m < 64; ++m) {
        unsigned int lo = __float_as_uint(trans[(2 * m) * NTAG + j]);
        unsigned int hi = __float_as_uint(trans[(2 * m + 1) * NTAG + j]);
        PACK_F32X2(trp[m], lo, hi);
        if (half == 0)
            *(float2*)(sm_tr + j * TRS + 2 * m) =
                make_float2(__uint_as_float(lo), __uint_as_float(hi));
    }

    const float* lg = logits + (long long)b * TMAX * NTAG;
    float* hist = g_hist + (long long)b * TMAX * NTAG;

    int L = seqlen[b];
    if (L < 1) L = 1;
    if (L > TMAX) L = TMAX;

    float s0 = lg[j];
    st[j] = s0;
    hist[j] = s0;
    __syncthreads();      // sm_tr + both st[0] ready

    // ---- Forward: max-only, 8 independent FMNMX chains ----
    for (int t = 1; t < L; ++t) {
        const float x = lg[t * NTAG + j];
        const ulonglong2* s2 = (const ulonglong2*)(st + ((t - 1) & 1) * NTAG);

        float best[8];
#pragma unroll
        for (int k = 0; k < 8; ++k) best[k] = -3.402823466e38f;

#pragma unroll
        for (int k = 0; k < 8; ++k) {
#pragma unroll
            for (int q = 0; q < 4; ++q) {
                ulonglong2 u = s2[k * 4 + q];
                unsigned long long r0, r1;
                ADD_F32X2(r0, u.x, trp[k * 8 + q * 2]);
                ADD_F32X2(r1, u.y, trp[k * 8 + q * 2 + 1]);
                unsigned int a0, a1, b0, b1;
                UNPACK_F32X2(a0, a1, r0);
                UNPACK_F32X2(b0, b1, r1);
                best[k] = fmaxf(best[k], __uint_as_float(a0));
                best[k] = fmaxf(best[k], __uint_as_float(a1));
                best[k] = fmaxf(best[k], __uint_as_float(b0));
                best[k] = fmaxf(best[k], __uint_as_float(b1));
            }
        }

        float bb = best[0];
#pragma unroll
        for (int k = 1; k < 8; ++k) bb = fmaxf(bb, best[k]);

        float nv = bb + x;
        st[(t & 1) * NTAG + j] = nv;
        hist[t * NTAG + j] = nv;
        half_bar(bar);
    }

    // Zero masked tail [L, T) — float output, d_out poisoned.
    float* orow = out + b * TMAX;
    for (int p = L + j; p < TMAX; p += NTAG)
        orow[p] = 0.0f;

    // ---- Backward: warp 0 of each half backtraces its sequence ----
    if (j < 32) {
        const int lane = j;
        const int i0 = lane * 4;
        const float* fs = st + ((L - 1) & 1) * NTAG;
        int cur;

        auto wargmax = [&](float v0, float v1, float v2, float v3) -> int {
            float best = v0; int lidx = 0; bool p;
            p = v1 > best; best = p ? v1 : best; lidx = p ? 1 : lidx;
            p = v2 > best; best = p ? v2 : best; lidx = p ? 2 : lidx;
            p = v3 > best; best = p ? v3 : best; lidx = p ? 3 : lidx;
            unsigned ub = ordered_u32(best);
            unsigned wm = __reduce_max_sync(0xFFFFFFFFu, ub);
            unsigned gi = (ub == wm) ? (unsigned)(i0 + lidx) : 0xFFFFFFFFu;
            return (int)__reduce_min_sync(0xFFFFFFFFu, gi);
        };

        {
            float4 h = *(const float4*)(fs + i0);
            cur = wargmax(h.x, h.y, h.z, h.w);
            if (lane == 0) orow[L - 1] = (float)cur;
        }

        auto step = [&](float4 hh, int tt) {
            float4 tv = *(const float4*)(sm_tr + cur * TRS + i0);
            cur = wargmax(hh.x + tv.x, hh.y + tv.y, hh.z + tv.z, hh.w + tv.w);
            if (lane == 0) orow[tt - 1] = (float)cur;
        };

        float4 bufA[8], bufB[8];
        auto load8 = [&](float4 (&buf)[8], int tb) {
#pragma unroll
            for (int k = 0; k < 8; ++k) {
                int r = tb - 1 - k;
                r = (r >= 0) ? r : 0;
                buf[k] = *(const float4*)(hist + r * NTAG + i0);
            }
        };

        int t = L - 1;
        if (t >= 1) {
            load8(bufA, t);
            while (true) {
                load8(bufB, t - 8);
#pragma unroll
                for (int k = 0; k < 8; ++k)
                    if (t - k >= 1) step(bufA[k], t - k);
                t -= 8;
                if (t < 1) break;

                load8(bufA, t - 8);
#pragma unroll
                for (int k = 0; k < 8; ++k)
                    if (t - k >= 1) step(bufB[k], t - k);
                t -= 8;
                if (t < 1) break;
            }
        }
    }
}

extern "C" void kernel_launch(void* const* d_in, const int* in_sizes, int n_in,
                              void* d_out, int out_size) {
    (void)in_sizes; (void)out_size;
    const void* p0 = d_in[0];
    const void* p1 = (n_in > 1) ? d_in[1] : d_in[0];
    const void* p2 = (n_in > 2) ? d_in[2] : d_in[0];
    float* out = (float*)d_out;

    const int smem_bytes = (4 * NTAG + NTAG * TRS) * 4;   // 69632
    cudaFuncSetAttribute(crf_fused_kernel,
                         cudaFuncAttributeMaxDynamicSharedMemorySize, smem_bytes);

    classify_kernel<<<1, BMAX>>>(p0, p1, p2);
    crf_fused_kernel<<<BMAX / 2, 2 * NTAG, smem_bytes>>>(p0, p1, p2, out);
}

// round 14
// speedup vs baseline: 1.1400x; 1.1400x over previous
#include <cuda_runtime.h>

// CRF Viterbi decode: B=256, T=512, N=128. Output dtype = FLOAT32.
// R14 vs R12: persistent-CTA LPT scheduling. Grid = 148 (one CTA per SM);
// each CTA pulls sequence ranks (longest-first, via device-side ranking)
// from a global atomic counter. Longest sequences get dedicated SMs and
// start first; near-optimal makespan. Forward/backward cores = R12.

constexpr int NTAG = 128;
constexpr int TMAX = 512;
constexpr int BMAX = 256;
constexpr int TRS  = 132;   // padded smem row stride (floats) for trT
constexpr int NSM  = 148;

__device__ float g_hist[(long long)BMAX * TMAX * NTAG];  // 64 MB state history
__device__ int g_perm[3];      // [0]=logits idx, [1]=transitions idx, [2]=seqlen idx
__device__ int g_sorted[BMAX]; // g_sorted[rank] = seq index (desc by length)
__device__ int g_work;         // work counter (reset by classify each replay)

#define ADD_F32X2(out, a, b) \
    asm("add.rn.f32x2 %0, %1, %2;" : "=l"(out) : "l"(a), "l"(b))
#define PACK_F32X2(out, lo, hi) \
    asm("mov.b64 %0, {%1, %2};" : "=l"(out) : "r"(lo), "r"(hi))
#define UNPACK_F32X2(lo, hi, in) \
    asm("mov.b64 {%0, %1}, %2;" : "=r"(lo), "=r"(hi) : "l"(in))

__global__ void classify_kernel(const void* p0, const void* p1, const void* p2)
{
    const int tid = threadIdx.x;
    __shared__ int sL[BMAX];
    const void* ptrs[3] = {p0, p1, p2};

    if (tid == 0) {
        g_work = 0;                       // reset work counter every replay
        int seq_idx = -1;
        float meanabs[3];
        for (int k = 0; k < 3; ++k) {
            const int*   wi = (const int*)ptrs[k];
            const float* wf = (const float*)ptrs[k];
            bool all_len = true;
            float s = 0.0f;
            for (int i = 0; i < 64; ++i) {
                int v = wi[i];
                if (v < 1 || v > TMAX) all_len = false;
                s += fabsf(wf[i]);
            }
            meanabs[k] = s * (1.0f / 64.0f);
            if (all_len && seq_idx < 0) seq_idx = k;
        }
        if (seq_idx < 0) seq_idx = 2;

        int a = -1, c = -1;
        for (int k = 0; k < 3; ++k)
            if (k != seq_idx) { if (a < 0) a = k; else c = k; }
        int tr = (meanabs[a] < meanabs[c]) ? a : c;
        int lg = (tr == a) ? c : a;
        g_perm[0] = lg; g_perm[1] = tr; g_perm[2] = seq_idx;
    }
    __syncthreads();

    // Rank sequences by length (descending, ties by index) -> g_sorted.
    const int* seqlen = (const int*)ptrs[g_perm[2]];
    int Li = seqlen[tid];
    if (Li < 1) Li = 1;
    if (Li > TMAX) Li = TMAX;
    sL[tid] = Li;
    __syncthreads();

    int r = 0;
    for (int k = 0; k < BMAX; ++k) {
        int Lk = sL[k];
        r += (Lk > Li) || (Lk == Li && k < tid);
    }
    g_sorted[r] = tid;
}

// Monotone order-preserving float->uint (equal floats -> equal uints).
__device__ __forceinline__ unsigned ordered_u32(float f) {
    unsigned u = __float_as_uint(f);
    return ((int)u >= 0) ? (u | 0x80000000u) : ~u;
}

__global__ void __launch_bounds__(128, 1)
crf_fused_kernel(const void* p0, const void* p1, const void* p2,
                 float* __restrict__ out)
{
    const void* ptrs[3] = {p0, p1, p2};
    const float* logits = (const float*)ptrs[g_perm[0]];
    const float* trans  = (const float*)ptrs[g_perm[1]];
    const int*   seqlen = (const int*)ptrs[g_perm[2]];

    extern __shared__ __align__(16) float dsm[];
    float* st    = dsm;             // 2 * NTAG state double buffer
    float* sm_tr = dsm + 2 * NTAG;  // sm_tr[j*TRS+i] = trans[i][j]
    __shared__ int s_rank;

    const int j = threadIdx.x;

    // Transition column j packed into 64 x f32x2, transposed into smem. Once.
    unsigned long long trp[64];
#pragma unroll
    for (int m = 0; m < 64; ++m) {
        unsigned int lo = __float_as_uint(trans[(2 * m) * NTAG + j]);
        unsigned int hi = __float_as_uint(trans[(2 * m + 1) * NTAG + j]);
        PACK_F32X2(trp[m], lo, hi);
        *(float2*)(sm_tr + j * TRS + 2 * m) =
            make_float2(__uint_as_float(lo), __uint_as_float(hi));
    }

    while (true) {
        __syncthreads();                 // protects s_rank + st reuse
        if (j == 0) s_rank = atomicAdd(&g_work, 1);
        __syncthreads();
        const int r = s_rank;
        if (r >= BMAX) break;            // uniform across CTA

        const int b = g_sorted[r];       // longest-first
        const float* lg = logits + (long long)b * TMAX * NTAG;
        float* hist = g_hist + (long long)b * TMAX * NTAG;

        int L = seqlen[b];
        if (L < 1) L = 1;
        if (L > TMAX) L = TMAX;

        float s0 = lg[j];
        st[j] = s0;
        hist[j] = s0;
        __syncthreads();

        // ---- Forward: max-only, 8 independent FMNMX chains ----
        for (int t = 1; t < L; ++t) {
            const float x = lg[t * NTAG + j];
            const ulonglong2* s2 = (const ulonglong2*)(st + ((t - 1) & 1) * NTAG);

            float best[8];
#pragma unroll
            for (int k = 0; k < 8; ++k) best[k] = -3.402823466e38f;

#pragma unroll
            for (int k = 0; k < 8; ++k) {
#pragma unroll
                for (int q = 0; q < 4; ++q) {
                    ulonglong2 u = s2[k * 4 + q];
                    unsigned long long r0, r1;
                    ADD_F32X2(r0, u.x, trp[k * 8 + q * 2]);
                    ADD_F32X2(r1, u.y, trp[k * 8 + q * 2 + 1]);
                    unsigned int a0, a1, b0, b1;
                    UNPACK_F32X2(a0, a1, r0);
                    UNPACK_F32X2(b0, b1, r1);
                    best[k] = fmaxf(best[k], __uint_as_float(a0));
                    best[k] = fmaxf(best[k], __uint_as_float(a1));
                    best[k] = fmaxf(best[k], __uint_as_float(b0));
                    best[k] = fmaxf(best[k], __uint_as_float(b1));
                }
            }

            float bb = best[0];
#pragma unroll
            for (int k = 1; k < 8; ++k) bb = fmaxf(bb, best[k]);

            float nv = bb + x;
            st[(t & 1) * NTAG + j] = nv;
            hist[t * NTAG + j] = nv;
            __syncthreads();
        }

        // Zero masked tail [L, T) — float output, d_out poisoned.
        float* orow = out + b * TMAX;
        for (int p = L + j; p < TMAX; p += NTAG)
            orow[p] = 0.0f;

        // ---- Backward: warp 0 backtraces this sequence ----
        if (j < 32) {
            const int lane = j;
            const int i0 = lane * 4;
            const float* fs = st + ((L - 1) & 1) * NTAG;
            int cur;

            auto wargmax = [&](float v0, float v1, float v2, float v3) -> int {
                float best = v0; int lidx = 0; bool p;
                p = v1 > best; best = p ? v1 : best; lidx = p ? 1 : lidx;
                p = v2 > best; best = p ? v2 : best; lidx = p ? 2 : lidx;
                p = v3 > best; best = p ? v3 : best; lidx = p ? 3 : lidx;
                unsigned ub = ordered_u32(best);
                unsigned wm = __reduce_max_sync(0xFFFFFFFFu, ub);
                unsigned gi = (ub == wm) ? (unsigned)(i0 + lidx) : 0xFFFFFFFFu;
                return (int)__reduce_min_sync(0xFFFFFFFFu, gi);
            };

            {
                float4 h = *(const float4*)(fs + i0);
                cur = wargmax(h.x, h.y, h.z, h.w);
                if (lane == 0) orow[L - 1] = (float)cur;
            }

            auto step = [&](float4 hh, int tt) {
                float4 tv = *(const float4*)(sm_tr + cur * TRS + i0);
                cur = wargmax(hh.x + tv.x, hh.y + tv.y, hh.z + tv.z, hh.w + tv.w);
                if (lane == 0) orow[tt - 1] = (float)cur;
            };

            float4 bufA[8], bufB[8];
            auto load8 = [&](float4 (&buf)[8], int tb) {
#pragma unroll
                for (int k = 0; k < 8; ++k) {
                    int rr = tb - 1 - k;
                    rr = (rr >= 0) ? rr : 0;
                    buf[k] = *(const float4*)(hist + rr * NTAG + i0);
                }
            };

            int t = L - 1;
            if (t >= 1) {
                load8(bufA, t);
                while (true) {
                    load8(bufB, t - 8);
#pragma unroll
                    for (int k = 0; k < 8; ++k)
                        if (t - k >= 1) step(bufA[k], t - k);
                    t -= 8;
                    if (t < 1) break;

                    load8(bufA, t - 8);
#pragma unroll
                    for (int k = 0; k < 8; ++k)
                        if (t - k >= 1) step(bufB[k], t - k);
                    t -= 8;
                    if (t < 1) break;
                }
            }
        }
    }
}

extern "C" void kernel_launch(void* const* d_in, const int* in_sizes, int n_in,
                              void* d_out, int out_size) {
    (void)in_sizes; (void)out_size;
    const void* p0 = d_in[0];
    const void* p1 = (n_in > 1) ? d_in[1] : d_in[0];
    const void* p2 = (n_in > 2) ? d_in[2] : d_in[0];
    float* out = (float*)d_out;

    const int smem_bytes = (2 * NTAG + NTAG * TRS) * 4;   // 68608
    cudaFuncSetAttribute(crf_fused_kernel,
                         cudaFuncAttributeMaxDynamicSharedMemorySize, smem_bytes);

    classify_kernel<<<1, BMAX>>>(p0, p1, p2);
    crf_fused_kernel<<<NSM, NTAG, smem_bytes>>>(p0, p1, p2, out);
}